// round 12
// baseline (speedup 1.0000x reference)
#include <cuda_runtime.h>
#include <cuda_bf16.h>
#include <stdint.h>

// BlankEmbedding: out[b,t,:] = emb[x[b,t]]
//   + sum_{j=1..3, t-j>=0} [x[b,t-j+1]==BLANK && x[b,t-j]!=BLANK] * emb[x[b,t-j]]
//
// B=4, S=4096, DIM=1024, VOCAB=50257, BLANK=100.
// HBM-bound: ~64MB gather read + ~64MB write. One 256-thread block per token
// row; each thread moves one float4. Blank hits are ~1/50257 so the
// conditional adds are almost never taken (no meaningful divergence/traffic).
//
// Token dtype (int64 vs int32) is auto-detected per grid-uniform check of the
// first 8 elements interpreted as int64: int32 data reinterpreted as int64
// yields values >= 2^32 unless the paired token is 0 (prob (1/50257)^8 ~ 0).

#define EB_VOCAB 50257
#define EB_DIM   1024
#define EB_BLANK 100
#define EB_S     4096
#define EB_B     4

__device__ __forceinline__ long long eb_tok(const void* __restrict__ x,
                                            int idx, bool is64) {
    if (is64) return __ldg(((const long long*)x) + idx);
    return (long long)__ldg(((const int*)x) + idx);
}

__global__ void __launch_bounds__(256, 8)
blank_emb_kernel(const void* __restrict__ x,
                 const float* __restrict__ emb,
                 float* __restrict__ out)
{
    // --- grid-uniform dtype detection (L1-broadcast loads, ~free) ---
    const long long* x64 = (const long long*)x;
    bool is64 = true;
#pragma unroll
    for (int i = 0; i < 8; i++) {
        long long v = __ldg(&x64[i]);
        if (v < 0 || v >= (long long)EB_VOCAB) is64 = false;
    }

    const int row = blockIdx.x;          // 0 .. B*S-1
    const int b   = row >> 12;           // row / S  (S = 4096)
    const int t   = row & (EB_S - 1);    // row % S
    const int tid = threadIdx.x;         // 0..255, one float4 each

    // main gather: emb[x[b,t]]
    const long long tok = eb_tok(x, row, is64);
    const float4* __restrict__ src =
        (const float4*)(emb + (size_t)tok * EB_DIM);
    float4 v = __ldg(&src[tid]);

    // preblank contributions from t-1, t-2, t-3 (rarely taken)
    const int base = b * EB_S;
#pragma unroll
    for (int j = 1; j <= 3; j++) {
        const int s = t - j;
        if (s >= 0) {
            const long long xnext = eb_tok(x, base + s + 1, is64);
            if (xnext == EB_BLANK) {
                const long long xs = eb_tok(x, base + s, is64);
                if (xs != EB_BLANK) {
                    const float4* __restrict__ p =
                        (const float4*)(emb + (size_t)xs * EB_DIM);
                    const float4 a = __ldg(&p[tid]);
                    v.x += a.x; v.y += a.y; v.z += a.z; v.w += a.w;
                }
            }
        }
    }

    ((float4*)(out + (size_t)row * EB_DIM))[tid] = v;
}

extern "C" void kernel_launch(void* const* d_in, const int* in_sizes, int n_in,
                              void* d_out, int out_size) {
    const void*  x   = d_in[0];               // [B,S] int64 or int32 tokens
    const float* emb = (const float*)d_in[1]; // [VOCAB, DIM] fp32
    float*       out = (float*)d_out;         // [B,S,DIM] fp32

    const int rows = EB_B * EB_S;             // 16384 blocks
    blank_emb_kernel<<<rows, 256>>>(x, emb, out);
}

// round 13
// speedup vs baseline: 1.2653x; 1.2653x over previous
#include <cuda_runtime.h>
#include <cuda_bf16.h>
#include <stdint.h>

// BlankEmbedding: out[b,t,:] = emb[x[b,t]]
//   + sum_{j=1..3, t-j>=0} [x[b,t-j+1]==BLANK && x[b,t-j]!=BLANK] * emb[x[b,t-j]]
//
// B=4, S=4096, DIM=1024, VOCAB=50257, BLANK=100.
//
// Two-kernel structure:
//   1) prepass: one thread per token row computes an int4 descriptor
//      {main_tok, add_tok0, add_tok1, add_tok2} (-1 = no add). All the
//      dtype-detection / token / index ALU happens here ONCE per row
//      (16K threads), not once per output element (4.2M threads).
//   2) main: 4 rows per 256-thread block. Each thread: 4 independent
//      float4 gathers (MLP=4), rare conditional adds, 4 streaming stores
//      (__stcs keeps the 64MB output from evicting the 196MB emb table
//      working set out of the 126MB L2).

#define EB_VOCAB 50257
#define EB_DIM   1024
#define EB_BLANK 100
#define EB_S     4096
#define EB_B     4
#define EB_ROWS  (EB_B * EB_S)   // 16384

__device__ int4 g_desc[EB_ROWS];

__device__ __forceinline__ int eb_tok(const void* __restrict__ x,
                                      int idx, bool is64) {
    if (is64) return (int)__ldg(((const long long*)x) + idx);
    return __ldg(((const int*)x) + idx);
}

// ---------------- prepass: build per-row descriptors ----------------
__global__ void __launch_bounds__(128)
blank_emb_prep(const void* __restrict__ x)
{
    const int row = blockIdx.x * 128 + threadIdx.x;   // 0..16383
    if (row >= EB_ROWS) return;

    // dtype detection: int32 data read as int64 is >= 2^32 (or negative)
    // unless the paired token is 0; P(8 false positives) ~ (1/50257)^8 ~ 0.
    const long long* x64 = (const long long*)x;
    bool is64 = true;
#pragma unroll
    for (int i = 0; i < 8; i++) {
        long long v = __ldg(&x64[i]);
        if (v < 0 || v >= (long long)EB_VOCAB) is64 = false;
    }

    const int b    = row >> 12;
    const int t    = row & (EB_S - 1);
    const int base = b << 12;

    int4 d;
    d.x = eb_tok(x, row, is64);
    d.y = -1; d.z = -1; d.w = -1;
    int* adds = &d.y;

#pragma unroll
    for (int j = 1; j <= 3; j++) {
        const int s = t - j;
        if (s >= 0) {
            // is_preblank[s] = (x[s+1]==BLANK) && (x[s]!=BLANK)
            if (eb_tok(x, base + s + 1, is64) == EB_BLANK) {
                const int xs = eb_tok(x, base + s, is64);
                if (xs != EB_BLANK) adds[j - 1] = xs;
            }
        }
    }
    g_desc[row] = d;
}

// ---------------- main: gather + rare adds + streaming store ----------------
__global__ void __launch_bounds__(256, 8)
blank_emb_main(const float* __restrict__ emb,
               float* __restrict__ out)
{
    __shared__ int4 sdesc[4];
    const int rbase = blockIdx.x << 2;     // 4 rows per block
    const int tid   = threadIdx.x;         // 0..255 -> one float4 per row

    if (tid < 4) sdesc[tid] = g_desc[rbase + tid];
    __syncthreads();

    // 4 independent gathers first (MLP=4)
    float4 v[4];
#pragma unroll
    for (int i = 0; i < 4; i++) {
        const float4* __restrict__ src =
            (const float4*)(emb + (size_t)sdesc[i].x * EB_DIM);
        v[i] = __ldg(&src[tid]);
    }

    // rare preblank adds (blank prob ~ 1/50257 -> almost never taken)
#pragma unroll
    for (int i = 0; i < 4; i++) {
        const int4 d = sdesc[i];
        if ((d.y | d.z | d.w) >= -1 && (d.y >= 0 || d.z >= 0 || d.w >= 0)) {
            const int a[3] = {d.y, d.z, d.w};
#pragma unroll
            for (int j = 0; j < 3; j++) {
                if (a[j] >= 0) {
                    const float4 e = __ldg(
                        (const float4*)(emb + (size_t)a[j] * EB_DIM) + tid);
                    v[i].x += e.x; v[i].y += e.y; v[i].z += e.z; v[i].w += e.w;
                }
            }
        }
    }

    // streaming stores: evict-first, don't pollute L2
#pragma unroll
    for (int i = 0; i < 4; i++) {
        __stcs((float4*)(out + (size_t)(rbase + i) * EB_DIM) + tid, v[i]);
    }
}

extern "C" void kernel_launch(void* const* d_in, const int* in_sizes, int n_in,
                              void* d_out, int out_size) {
    const void*  x   = d_in[0];               // [B,S] tokens (int64 or int32)
    const float* emb = (const float*)d_in[1]; // [VOCAB, DIM] fp32
    float*       out = (float*)d_out;         // [B,S,DIM] fp32

    blank_emb_prep<<<(EB_ROWS + 127) / 128, 128>>>(x);
    blank_emb_main<<<EB_ROWS / 4, 256>>>(emb, out);
}